// round 4
// baseline (speedup 1.0000x reference)
#include <cuda_runtime.h>
#include <cuda_bf16.h>
#include <cstdint>

#define DD    32
#define KK    192          // 6 groups of 32: [qh*wh, qh*wl, ql*wh, ph*ah, ph*al, pl*ah]
#define KPAD  200          // bf16 elems per smem row: 400B stride -> ldmatrix conflict-free
#define TNPTS 128          // x points per block   (GEMM M)
#define TMC   128          // centers per block    (GEMM N)
#define MMAX  1024

__device__ __nv_bfloat16 g_B[MMAX * KK];  // [m][k] bf16, CEXP pre-folded
__device__ float g_eb[MMAX];              // CEXP*sum(c^2/s^2) + log2(1/detS)

// ---------------- helpers ----------------
__device__ __forceinline__ uint32_t smem_u32(const void* p) {
    uint32_t a;
    asm("{ .reg .u64 t; cvta.to.shared.u64 t, %1; cvt.u32.u64 %0, t; }" : "=r"(a) : "l"(p));
    return a;
}
__device__ __forceinline__ float ex2(float v) {
    float r; asm("ex2.approx.ftz.f32 %0, %1;" : "=f"(r) : "f"(v)); return r;
}
__device__ __forceinline__ void ldsm_x4(uint32_t& r0, uint32_t& r1, uint32_t& r2, uint32_t& r3,
                                        uint32_t addr) {
    asm volatile("ldmatrix.sync.aligned.m8n8.x4.shared.b16 {%0,%1,%2,%3}, [%4];"
                 : "=r"(r0), "=r"(r1), "=r"(r2), "=r"(r3) : "r"(addr));
}
__device__ __forceinline__ void mma_bf16(float* c, const uint32_t* a, uint32_t b0, uint32_t b1) {
    asm volatile(
        "mma.sync.aligned.m16n8k16.row.col.f32.bf16.bf16.f32 "
        "{%0,%1,%2,%3}, {%4,%5,%6,%7}, {%8,%9}, {%0,%1,%2,%3};"
        : "+f"(c[0]), "+f"(c[1]), "+f"(c[2]), "+f"(c[3])
        : "r"(a[0]), "r"(a[1]), "r"(a[2]), "r"(a[3]), "r"(b0), "r"(b1));
}

// ---------------- precompute B + eb ----------------
__global__ void rbf_precompute(const float* __restrict__ centers,
                               const float* __restrict__ sigma, int M) {
    int m = blockIdx.x * blockDim.x + threadIdx.x;
    if (m >= M) return;
    const float CEXP = -0.7213475204444817f;     // -0.5 * log2(e)
    const float LOG2_2PI = 2.6514961294723187f;
    float cm = 0.0f, lg = 0.0f;
    __nv_bfloat16* b = g_B + (size_t)m * KK;
#pragma unroll
    for (int d = 0; d < DD; d++) {
        float c  = centers[m * DD + d];
        float s  = sigma[m * DD + d];
        float s2 = s * s;
        float w  = CEXP / s2;          // CEXP folded in
        float a  = -2.0f * c * w;
        __nv_bfloat16 wh = __float2bfloat16_rn(w);
        __nv_bfloat16 wl = __float2bfloat16_rn(w - __bfloat162float(wh));
        __nv_bfloat16 ah = __float2bfloat16_rn(a);
        __nv_bfloat16 al = __float2bfloat16_rn(a - __bfloat162float(ah));
        b[0 * 32 + d] = wh;  b[1 * 32 + d] = wl;  b[2 * 32 + d] = wh;
        b[3 * 32 + d] = ah;  b[4 * 32 + d] = al;  b[5 * 32 + d] = ah;
        cm = fmaf(c * c, 1.0f / s2, cm);
        lg += log2f(s2);
    }
    g_eb[m] = fmaf(CEXP, cm, -0.5f * (DD * LOG2_2PI + lg));
}

// ---------------- main GEMM + exp epilogue ----------------
__global__ __launch_bounds__(256, 1)
void rbf_gemm(const float* __restrict__ x, float* __restrict__ out, int N, int M) {
    extern __shared__ char dyn[];
    __nv_bfloat16* a_s  = (__nv_bfloat16*)dyn;                       // [128][KPAD]
    __nv_bfloat16* b_s  = a_s + TNPTS * KPAD;                        // [128][KPAD]
    float*         eb_s = (float*)(b_s + TMC * KPAD);                // [128]

    const int tid  = threadIdx.x;
    const int wid  = tid >> 5;
    const int lane = tid & 31;
    const int n0 = blockIdx.y * TNPTS;   // x-point base
    const int m0 = blockIdx.x * TMC;     // center base

    // --- Build A tile: split x and x^2 into bf16 hi/lo, group layout matching B ---
    {
        int row = tid >> 1;
        int ds  = (tid & 1) * 16;
        float xv[16];
        const float4* xr = (const float4*)(x + (size_t)(n0 + row) * DD + ds);
#pragma unroll
        for (int i = 0; i < 4; i++) {
            float4 v = xr[i];
            xv[i * 4 + 0] = v.x; xv[i * 4 + 1] = v.y; xv[i * 4 + 2] = v.z; xv[i * 4 + 3] = v.w;
        }
        __nv_bfloat16 qh[16], ql[16], ph[16], pl[16];
#pragma unroll
        for (int i = 0; i < 16; i++) {
            float v = xv[i];
            ph[i] = __float2bfloat16_rn(v);
            pl[i] = __float2bfloat16_rn(v - __bfloat162float(ph[i]));
            float q = v * v;
            qh[i] = __float2bfloat16_rn(q);
            ql[i] = __float2bfloat16_rn(q - __bfloat162float(qh[i]));
        }
        __nv_bfloat16* arow = a_s + row * KPAD + ds;
        const __nv_bfloat16* gsel[6] = {qh, qh, ql, ph, ph, pl};
#pragma unroll
        for (int g = 0; g < 6; g++) {
            const __nv_bfloat16* sp = gsel[g];
#pragma unroll
            for (int i = 0; i < 16; i += 2) {
                __nv_bfloat162 pr; pr.x = sp[i]; pr.y = sp[i + 1];
                *(__nv_bfloat162*)(arow + g * 32 + i) = pr;
            }
        }
    }
    // --- Load B tile (128 centers x 192 bf16 = 24 int4 chunks/row) ---
    for (int i = tid; i < TMC * 24; i += 256) {
        int mrow = i / 24;
        int c    = i - mrow * 24;
        int4 v = *(const int4*)((const char*)(g_B + (size_t)(m0 + mrow) * KK) + c * 16);
        *(int4*)((char*)(b_s + mrow * KPAD) + c * 16) = v;
    }
    if (tid < TMC) eb_s[tid] = g_eb[m0 + tid];
    __syncthreads();

    // --- Warp tiling: 2 (m) x 4 (n) warps; warp tile 64 x 32 ---
    const int warp_m = (wid & 1) * 64;
    const int warp_n = (wid >> 1) * 32;

    // ldmatrix base addresses
    uint32_t a_base = smem_u32(a_s) + (uint32_t)(warp_m + (lane & 15)) * (KPAD * 2)
                    + ((uint32_t)lane >> 4) * 16u;
    uint32_t b_base = smem_u32(b_s)
                    + (uint32_t)(warp_n + ((lane >> 4) & 1) * 8 + (lane & 7)) * (KPAD * 2)
                    + (uint32_t)((lane >> 3) & 1) * 16u;

    float acc[4][4][4];
#pragma unroll
    for (int i = 0; i < 4; i++)
#pragma unroll
        for (int j = 0; j < 4; j++)
#pragma unroll
            for (int k = 0; k < 4; k++) acc[i][j][k] = 0.0f;

#pragma unroll
    for (int s = 0; s < KK / 16; s++) {
        uint32_t af[4][4];
#pragma unroll
        for (int mi = 0; mi < 4; mi++)
            ldsm_x4(af[mi][0], af[mi][1], af[mi][2], af[mi][3],
                    a_base + (uint32_t)mi * (16 * KPAD * 2) + (uint32_t)s * 32u);
        uint32_t bf[4][2];
#pragma unroll
        for (int nj2 = 0; nj2 < 2; nj2++) {
            uint32_t r0, r1, r2, r3;
            ldsm_x4(r0, r1, r2, r3,
                    b_base + (uint32_t)nj2 * (16 * KPAD * 2) + (uint32_t)s * 32u);
            bf[nj2 * 2 + 0][0] = r0; bf[nj2 * 2 + 0][1] = r1;
            bf[nj2 * 2 + 1][0] = r2; bf[nj2 * 2 + 1][1] = r3;
        }
#pragma unroll
        for (int mi = 0; mi < 4; mi++)
#pragma unroll
            for (int nt = 0; nt < 4; nt++)
                mma_bf16(acc[mi][nt], af[mi], bf[nt][0], bf[nt][1]);
    }

    // --- Epilogue: out = exp2(acc + eb) ---
    const int qrow = lane >> 2;
    const int qcol = 2 * (lane & 3);
#pragma unroll
    for (int mi = 0; mi < 4; mi++) {
        int row0 = n0 + warp_m + mi * 16 + qrow;
#pragma unroll
        for (int nt = 0; nt < 4; nt++) {
            int col_l = warp_n + nt * 8 + qcol;
            float2 ebv = *(const float2*)(eb_s + col_l);
            float* p0 = out + (size_t)row0 * M + m0 + col_l;
            float2 r0, r1;
            r0.x = ex2(acc[mi][nt][0] + ebv.x);
            r0.y = ex2(acc[mi][nt][1] + ebv.y);
            r1.x = ex2(acc[mi][nt][2] + ebv.x);
            r1.y = ex2(acc[mi][nt][3] + ebv.y);
            *(float2*)(p0) = r0;
            *(float2*)(p0 + (size_t)8 * M) = r1;
        }
    }
}

extern "C" void kernel_launch(void* const* d_in, const int* in_sizes, int n_in,
                              void* d_out, int out_size) {
    const float* x       = (const float*)d_in[0];
    const float* centers = (const float*)d_in[1];
    const float* sigma   = (const float*)d_in[2];
    float* out = (float*)d_out;

    int N = in_sizes[0] / DD;
    int M = in_sizes[1] / DD;

    rbf_precompute<<<(M + 127) / 128, 128>>>(centers, sigma, M);

    const int SMEM_BYTES = TNPTS * KPAD * 2 + TMC * KPAD * 2 + TMC * 4;  // ~102.9 KB
    cudaFuncSetAttribute(rbf_gemm, cudaFuncAttributeMaxDynamicSharedMemorySize, SMEM_BYTES);

    dim3 grid(M / TMC, N / TNPTS);
    rbf_gemm<<<grid, 256, SMEM_BYTES>>>(x, out, N, M);
}

// round 5
// speedup vs baseline: 2.3490x; 2.3490x over previous
#include <cuda_runtime.h>
#include <cuda_bf16.h>
#include <cstdint>

#define DD    32
#define KK    192          // 6 groups of 32: A=(qh,qh,ql,ph,ph,pl) * B=(wh,wl,wh,ah,al,ah)
#define KPAD  200          // bf16 per smem row: 400B stride -> ldmatrix conflict-free
#define TNPTS 128          // x points per block   (GEMM M)
#define TMC   128          // centers per block    (GEMM N)
#define MMAX  1024

__device__ __nv_bfloat16 g_B[MMAX * KK];  // [m][k] bf16, CEXP pre-folded
__device__ float g_eb[MMAX];              // CEXP*sum(c^2/s^2) + log2(1/detS)

// ---------------- helpers ----------------
__device__ __forceinline__ uint32_t smem_u32(const void* p) {
    uint32_t a;
    asm("{ .reg .u64 t; cvta.to.shared.u64 t, %1; cvt.u32.u64 %0, t; }" : "=r"(a) : "l"(p));
    return a;
}
__device__ __forceinline__ float ex2(float v) {
    float r; asm("ex2.approx.ftz.f32 %0, %1;" : "=f"(r) : "f"(v)); return r;
}
__device__ __forceinline__ void ldsm_x4(uint32_t& r0, uint32_t& r1, uint32_t& r2, uint32_t& r3,
                                        uint32_t addr) {
    asm volatile("ldmatrix.sync.aligned.m8n8.x4.shared.b16 {%0,%1,%2,%3}, [%4];"
                 : "=r"(r0), "=r"(r1), "=r"(r2), "=r"(r3) : "r"(addr));
}
__device__ __forceinline__ void mma_bf16(float* c, const uint32_t* a, uint32_t b0, uint32_t b1) {
    asm volatile(
        "mma.sync.aligned.m16n8k16.row.col.f32.bf16.bf16.f32 "
        "{%0,%1,%2,%3}, {%4,%5,%6,%7}, {%8,%9}, {%0,%1,%2,%3};"
        : "+f"(c[0]), "+f"(c[1]), "+f"(c[2]), "+f"(c[3])
        : "r"(a[0]), "r"(a[1]), "r"(a[2]), "r"(a[3]), "r"(b0), "r"(b1));
}

// ---------------- precompute B + eb (smem-staged, coalesced writeout) ----------------
__global__ void rbf_precompute(const float* __restrict__ centers,
                               const float* __restrict__ sigma, int M) {
    extern __shared__ __nv_bfloat16 sB[];    // [128][KPAD]
    int tid = threadIdx.x;                   // 128 threads
    int m0  = blockIdx.x * 128;
    int m   = m0 + tid;

    const float CEXP = -0.7213475204444817f;     // -0.5 * log2(e)
    const float LOG2_2PI = 2.6514961294723187f;
    float cm = 0.0f, lg = 0.0f;
    __nv_bfloat16* row = sB + tid * KPAD;
#pragma unroll
    for (int d = 0; d < DD; d++) {
        float c  = centers[m * DD + d];
        float s  = sigma[m * DD + d];
        float s2 = s * s;
        float w  = CEXP / s2;          // CEXP folded in
        float a  = -2.0f * c * w;
        __nv_bfloat16 wh = __float2bfloat16_rn(w);
        __nv_bfloat16 wl = __float2bfloat16_rn(w - __bfloat162float(wh));
        __nv_bfloat16 ah = __float2bfloat16_rn(a);
        __nv_bfloat16 al = __float2bfloat16_rn(a - __bfloat162float(ah));
        row[0 * 32 + d] = wh;  row[1 * 32 + d] = wl;  row[2 * 32 + d] = wh;
        row[3 * 32 + d] = ah;  row[4 * 32 + d] = al;  row[5 * 32 + d] = ah;
        cm = fmaf(c * c, 1.0f / s2, cm);
        lg += log2f(s2);
    }
    g_eb[m] = fmaf(CEXP, cm, -0.5f * (DD * LOG2_2PI + lg));
    __syncthreads();
    // coalesced writeout: 128 rows x 24 int4 chunks
    for (int idx = tid; idx < 128 * 24; idx += 128) {
        int mrow = idx / 24;
        int c    = idx - mrow * 24;
        int4 v = *(const int4*)((const char*)(sB + mrow * KPAD) + c * 16);
        *(int4*)((char*)(g_B + (size_t)(m0 + mrow) * KK) + c * 16) = v;
    }
}

// ---------------- main GEMM + exp epilogue ----------------
__global__ __launch_bounds__(256, 2)
void rbf_gemm(const float* __restrict__ x, float* __restrict__ out, int N, int M) {
    extern __shared__ char dyn[];
    __nv_bfloat16* a_s  = (__nv_bfloat16*)dyn;                       // [128][KPAD]
    __nv_bfloat16* b_s  = a_s + TNPTS * KPAD;                        // [128][KPAD]
    float*         eb_s = (float*)(b_s + TMC * KPAD);                // [128]

    const int tid  = threadIdx.x;
    const int wid  = tid >> 5;
    const int lane = tid & 31;
    const int n0 = blockIdx.y * TNPTS;   // x-point base
    const int m0 = blockIdx.x * TMC;     // center base

    // --- Build A tile: split x and x^2 into bf16 hi/lo, group layout matching B ---
    {
        int row = tid >> 1;
        int ds  = (tid & 1) * 16;
        float xv[16];
        const float4* xr = (const float4*)(x + (size_t)(n0 + row) * DD + ds);
#pragma unroll
        for (int i = 0; i < 4; i++) {
            float4 v = xr[i];
            xv[i * 4 + 0] = v.x; xv[i * 4 + 1] = v.y; xv[i * 4 + 2] = v.z; xv[i * 4 + 3] = v.w;
        }
        __nv_bfloat16 qh[16], ql[16], ph[16], pl[16];
#pragma unroll
        for (int i = 0; i < 16; i++) {
            float v = xv[i];
            ph[i] = __float2bfloat16_rn(v);
            pl[i] = __float2bfloat16_rn(v - __bfloat162float(ph[i]));
            float q = v * v;
            qh[i] = __float2bfloat16_rn(q);
            ql[i] = __float2bfloat16_rn(q - __bfloat162float(qh[i]));
        }
        __nv_bfloat16* arow = a_s + row * KPAD + ds;
        const __nv_bfloat16* gsel[6] = {qh, qh, ql, ph, ph, pl};
#pragma unroll
        for (int g = 0; g < 6; g++) {
            const __nv_bfloat16* sp = gsel[g];
#pragma unroll
            for (int i = 0; i < 16; i += 2) {
                __nv_bfloat162 pr; pr.x = sp[i]; pr.y = sp[i + 1];
                *(__nv_bfloat162*)(arow + g * 32 + i) = pr;
            }
        }
    }
    // --- Load B tile (128 centers x 192 bf16 = 24 int4 chunks/row) ---
    for (int i = tid; i < TMC * 24; i += 256) {
        int mrow = i / 24;
        int c    = i - mrow * 24;
        int4 v = *(const int4*)((const char*)(g_B + (size_t)(m0 + mrow) * KK) + c * 16);
        *(int4*)((char*)(b_s + mrow * KPAD) + c * 16) = v;
    }
    if (tid < TMC) eb_s[tid] = g_eb[m0 + tid];
    __syncthreads();

    // --- Warp tiling: 2 (m) x 4 (n) warps; warp tile 64 x 32 ---
    const int warp_m = (wid & 1) * 64;
    const int warp_n = (wid >> 1) * 32;

    uint32_t a_base = smem_u32(a_s) + (uint32_t)(warp_m + (lane & 15)) * (KPAD * 2)
                    + ((uint32_t)lane >> 4) * 16u;
    uint32_t b_base = smem_u32(b_s)
                    + (uint32_t)(warp_n + ((lane >> 4) & 1) * 8 + (lane & 7)) * (KPAD * 2)
                    + (uint32_t)((lane >> 3) & 1) * 16u;

    float acc[4][4][4];
#pragma unroll
    for (int i = 0; i < 4; i++)
#pragma unroll
        for (int j = 0; j < 4; j++)
#pragma unroll
            for (int k = 0; k < 4; k++) acc[i][j][k] = 0.0f;

#pragma unroll
    for (int s = 0; s < KK / 16; s++) {
        uint32_t af[4][4];
#pragma unroll
        for (int mi = 0; mi < 4; mi++)
            ldsm_x4(af[mi][0], af[mi][1], af[mi][2], af[mi][3],
                    a_base + (uint32_t)mi * (16 * KPAD * 2) + (uint32_t)s * 32u);
        uint32_t bf[4][2];
#pragma unroll
        for (int nj2 = 0; nj2 < 2; nj2++) {
            uint32_t r0, r1, r2, r3;
            ldsm_x4(r0, r1, r2, r3,
                    b_base + (uint32_t)nj2 * (16 * KPAD * 2) + (uint32_t)s * 32u);
            bf[nj2 * 2 + 0][0] = r0; bf[nj2 * 2 + 0][1] = r1;
            bf[nj2 * 2 + 1][0] = r2; bf[nj2 * 2 + 1][1] = r3;
        }
#pragma unroll
        for (int mi = 0; mi < 4; mi++)
#pragma unroll
            for (int nt = 0; nt < 4; nt++)
                mma_bf16(acc[mi][nt], af[mi], bf[nt][0], bf[nt][1]);
    }

    // --- Epilogue: out = exp2(acc + eb) ---
    const int qrow = lane >> 2;
    const int qcol = 2 * (lane & 3);
#pragma unroll
    for (int mi = 0; mi < 4; mi++) {
        int row0 = n0 + warp_m + mi * 16 + qrow;
#pragma unroll
        for (int nt = 0; nt < 4; nt++) {
            int col_l = warp_n + nt * 8 + qcol;
            float2 ebv = *(const float2*)(eb_s + col_l);
            float* p0 = out + (size_t)row0 * M + m0 + col_l;
            float2 r0, r1;
            r0.x = ex2(acc[mi][nt][0] + ebv.x);
            r0.y = ex2(acc[mi][nt][1] + ebv.y);
            r1.x = ex2(acc[mi][nt][2] + ebv.x);
            r1.y = ex2(acc[mi][nt][3] + ebv.y);
            *(float2*)(p0) = r0;
            *(float2*)(p0 + (size_t)8 * M) = r1;
        }
    }
}

extern "C" void kernel_launch(void* const* d_in, const int* in_sizes, int n_in,
                              void* d_out, int out_size) {
    const float* x       = (const float*)d_in[0];
    const float* centers = (const float*)d_in[1];
    const float* sigma   = (const float*)d_in[2];
    float* out = (float*)d_out;

    int N = in_sizes[0] / DD;
    int M = in_sizes[1] / DD;

    const int PRE_SMEM = 128 * KPAD * 2;                               // 50 KB
    cudaFuncSetAttribute(rbf_precompute, cudaFuncAttributeMaxDynamicSharedMemorySize, PRE_SMEM);
    rbf_precompute<<<M / 128, 128, PRE_SMEM>>>(centers, sigma, M);

    const int SMEM_BYTES = TNPTS * KPAD * 2 + TMC * KPAD * 2 + TMC * 4;  // ~102.9 KB
    cudaFuncSetAttribute(rbf_gemm, cudaFuncAttributeMaxDynamicSharedMemorySize, SMEM_BYTES);

    dim3 grid(M / TMC, N / TNPTS);
    rbf_gemm<<<grid, 256, SMEM_BYTES>>>(x, out, N, M);
}

// round 6
// speedup vs baseline: 2.5266x; 1.0756x over previous
#include <cuda_runtime.h>
#include <cuda_bf16.h>
#include <cstdint>

#define DD    32
#define KK    192          // 6 groups of 32: A=(qh,qh,ql,ph,ph,pl) * B=(wh,wl,wh,ah,al,ah)
#define KPAD  200          // bf16 per smem row: 400B stride -> ldmatrix conflict-free
#define NROW  24           // int4 chunks per 192-bf16 row
#define TNPTS 128
#define TMC   128
#define NMAX  16384
#define MMAX  1024

__device__ __nv_bfloat16 g_A[NMAX * KK];  // [n][k] bf16 split of (x^2, x)
__device__ __nv_bfloat16 g_B[MMAX * KK];  // [m][k] bf16, CEXP pre-folded
__device__ float g_eb[MMAX];              // CEXP*sum(c^2/s^2) + log2(1/detS)

// ---------------- helpers ----------------
__device__ __forceinline__ uint32_t smem_u32(const void* p) {
    uint32_t a;
    asm("{ .reg .u64 t; cvta.to.shared.u64 t, %1; cvt.u32.u64 %0, t; }" : "=r"(a) : "l"(p));
    return a;
}
__device__ __forceinline__ float ex2(float v) {
    float r; asm("ex2.approx.ftz.f32 %0, %1;" : "=f"(r) : "f"(v)); return r;
}
__device__ __forceinline__ void cp16(uint32_t smem_addr, const void* gptr) {
    asm volatile("cp.async.cg.shared.global [%0], [%1], 16;" :: "r"(smem_addr), "l"(gptr));
}
__device__ __forceinline__ void ldsm_x4(uint32_t& r0, uint32_t& r1, uint32_t& r2, uint32_t& r3,
                                        uint32_t addr) {
    asm volatile("ldmatrix.sync.aligned.m8n8.x4.shared.b16 {%0,%1,%2,%3}, [%4];"
                 : "=r"(r0), "=r"(r1), "=r"(r2), "=r"(r3) : "r"(addr));
}
__device__ __forceinline__ void mma_bf16(float* c, const uint32_t* a, uint32_t b0, uint32_t b1) {
    asm volatile(
        "mma.sync.aligned.m16n8k16.row.col.f32.bf16.bf16.f32 "
        "{%0,%1,%2,%3}, {%4,%5,%6,%7}, {%8,%9}, {%0,%1,%2,%3};"
        : "+f"(c[0]), "+f"(c[1]), "+f"(c[2]), "+f"(c[3])
        : "r"(a[0]), "r"(a[1]), "r"(a[2]), "r"(a[3]), "r"(b0), "r"(b1));
}
__device__ __forceinline__ __nv_bfloat16 bfh(float v) { return __float2bfloat16_rn(v); }

// ---------------- precompute A (x splits), smem-staged ----------------
__global__ void rbf_precompute_A(const float* __restrict__ x, int N) {
    extern __shared__ __nv_bfloat16 sA[];     // [128][KPAD]
    int tid = threadIdx.x;                    // 128 threads
    int n0  = blockIdx.x * 128;
    const float4* xr = (const float4*)(x + (size_t)(n0 + tid) * DD);
    __nv_bfloat16* row = sA + tid * KPAD;
#pragma unroll
    for (int i4 = 0; i4 < 8; i4++) {
        float4 v4 = xr[i4];
        float vv[4] = {v4.x, v4.y, v4.z, v4.w};
#pragma unroll
        for (int j = 0; j < 4; j++) {
            int d = i4 * 4 + j;
            float v = vv[j];
            __nv_bfloat16 ph = bfh(v);
            __nv_bfloat16 pl = bfh(v - __bfloat162float(ph));
            float q = v * v;
            __nv_bfloat16 qh = bfh(q);
            __nv_bfloat16 ql = bfh(q - __bfloat162float(qh));
            row[0 * 32 + d] = qh;  row[1 * 32 + d] = qh;  row[2 * 32 + d] = ql;
            row[3 * 32 + d] = ph;  row[4 * 32 + d] = ph;  row[5 * 32 + d] = pl;
        }
    }
    __syncthreads();
    for (int idx = tid; idx < 128 * NROW; idx += 128) {
        int r = idx / NROW, c = idx - r * NROW;
        int4 v = *(const int4*)((const char*)(sA + r * KPAD) + c * 16);
        *(int4*)((char*)(g_A + (size_t)(n0 + r) * KK) + c * 16) = v;
    }
}

// ---------------- precompute B + eb, smem-staged ----------------
__global__ void rbf_precompute_B(const float* __restrict__ centers,
                                 const float* __restrict__ sigma, int M) {
    extern __shared__ __nv_bfloat16 sB[];     // [128][KPAD]
    int tid = threadIdx.x;                    // 128 threads
    int m0  = blockIdx.x * 128;
    int m   = m0 + tid;

    const float CEXP = -0.7213475204444817f;  // -0.5 * log2(e)
    const float LOG2_2PI = 2.6514961294723187f;
    float cm = 0.0f, lg = 0.0f;
    __nv_bfloat16* row = sB + tid * KPAD;
#pragma unroll
    for (int d = 0; d < DD; d++) {
        float c  = centers[m * DD + d];
        float s  = sigma[m * DD + d];
        float s2 = s * s;
        float w  = CEXP / s2;
        float a  = -2.0f * c * w;
        __nv_bfloat16 wh = bfh(w);
        __nv_bfloat16 wl = bfh(w - __bfloat162float(wh));
        __nv_bfloat16 ah = bfh(a);
        __nv_bfloat16 al = bfh(a - __bfloat162float(ah));
        row[0 * 32 + d] = wh;  row[1 * 32 + d] = wl;  row[2 * 32 + d] = wh;
        row[3 * 32 + d] = ah;  row[4 * 32 + d] = al;  row[5 * 32 + d] = ah;
        cm = fmaf(c * c, 1.0f / s2, cm);
        lg += log2f(s2);
    }
    g_eb[m] = fmaf(CEXP, cm, -0.5f * (DD * LOG2_2PI + lg));
    __syncthreads();
    for (int idx = tid; idx < 128 * NROW; idx += 128) {
        int r = idx / NROW, c = idx - r * NROW;
        int4 v = *(const int4*)((const char*)(sB + r * KPAD) + c * 16);
        *(int4*)((char*)(g_B + (size_t)(m0 + r) * KK) + c * 16) = v;
    }
}

// ---------------- main GEMM + exp epilogue ----------------
__global__ __launch_bounds__(256, 2)
void rbf_gemm(float* __restrict__ out, int N, int M) {
    extern __shared__ char dyn[];
    __nv_bfloat16* a_s  = (__nv_bfloat16*)dyn;            // [128][KPAD]
    __nv_bfloat16* b_s  = a_s + TNPTS * KPAD;             // [128][KPAD]
    float*         eb_s = (float*)(b_s + TMC * KPAD);     // [128]

    const int tid  = threadIdx.x;
    const int wid  = tid >> 5;
    const int lane = tid & 31;
    const int n0 = blockIdx.y * TNPTS;
    const int m0 = blockIdx.x * TMC;

    // --- Async tile loads: A then B, 24 int4/row, conflict-free, coalesced ---
    {
        uint32_t a_u = smem_u32(a_s), b_u = smem_u32(b_s);
        for (int i = tid; i < TNPTS * NROW; i += 256) {
            int r = i / NROW, c = i - r * NROW;
            cp16(a_u + (uint32_t)(r * (KPAD * 2) + c * 16),
                 (const char*)(g_A + (size_t)(n0 + r) * KK) + c * 16);
        }
        for (int i = tid; i < TMC * NROW; i += 256) {
            int r = i / NROW, c = i - r * NROW;
            cp16(b_u + (uint32_t)(r * (KPAD * 2) + c * 16),
                 (const char*)(g_B + (size_t)(m0 + r) * KK) + c * 16);
        }
        asm volatile("cp.async.commit_group;" ::: "memory");
    }
    if (tid < TMC) eb_s[tid] = g_eb[m0 + tid];
    asm volatile("cp.async.wait_group 0;" ::: "memory");
    __syncthreads();

    // --- Warp tiling: 2 (m) x 4 (n) warps; warp tile 64 x 32 ---
    const int warp_m = (wid & 1) * 64;
    const int warp_n = (wid >> 1) * 32;

    uint32_t a_base = smem_u32(a_s) + (uint32_t)(warp_m + (lane & 15)) * (KPAD * 2)
                    + ((uint32_t)lane >> 4) * 16u;
    uint32_t b_base = smem_u32(b_s)
                    + (uint32_t)(warp_n + ((lane >> 4) & 1) * 8 + (lane & 7)) * (KPAD * 2)
                    + (uint32_t)((lane >> 3) & 1) * 16u;

    float acc[4][4][4];
#pragma unroll
    for (int i = 0; i < 4; i++)
#pragma unroll
        for (int j = 0; j < 4; j++)
#pragma unroll
            for (int k = 0; k < 4; k++) acc[i][j][k] = 0.0f;

#pragma unroll
    for (int s = 0; s < KK / 16; s++) {
        uint32_t af[4][4];
#pragma unroll
        for (int mi = 0; mi < 4; mi++)
            ldsm_x4(af[mi][0], af[mi][1], af[mi][2], af[mi][3],
                    a_base + (uint32_t)mi * (16 * KPAD * 2) + (uint32_t)s * 32u);
        uint32_t bf[4][2];
#pragma unroll
        for (int nj2 = 0; nj2 < 2; nj2++) {
            uint32_t r0, r1, r2, r3;
            ldsm_x4(r0, r1, r2, r3,
                    b_base + (uint32_t)nj2 * (16 * KPAD * 2) + (uint32_t)s * 32u);
            bf[nj2 * 2 + 0][0] = r0; bf[nj2 * 2 + 0][1] = r1;
            bf[nj2 * 2 + 1][0] = r2; bf[nj2 * 2 + 1][1] = r3;
        }
#pragma unroll
        for (int mi = 0; mi < 4; mi++)
#pragma unroll
            for (int nt = 0; nt < 4; nt++)
                mma_bf16(acc[mi][nt], af[mi], bf[nt][0], bf[nt][1]);
    }

    // --- Epilogue: out = exp2(acc + eb) ---
    const int qrow = lane >> 2;
    const int qcol = 2 * (lane & 3);
#pragma unroll
    for (int mi = 0; mi < 4; mi++) {
        int row0 = n0 + warp_m + mi * 16 + qrow;
#pragma unroll
        for (int nt = 0; nt < 4; nt++) {
            int col_l = warp_n + nt * 8 + qcol;
            float2 ebv = *(const float2*)(eb_s + col_l);
            float* p0 = out + (size_t)row0 * M + m0 + col_l;
            float2 r0, r1;
            r0.x = ex2(acc[mi][nt][0] + ebv.x);
            r0.y = ex2(acc[mi][nt][1] + ebv.y);
            r1.x = ex2(acc[mi][nt][2] + ebv.x);
            r1.y = ex2(acc[mi][nt][3] + ebv.y);
            *(float2*)(p0) = r0;
            *(float2*)(p0 + (size_t)8 * M) = r1;
        }
    }
}

extern "C" void kernel_launch(void* const* d_in, const int* in_sizes, int n_in,
                              void* d_out, int out_size) {
    const float* x       = (const float*)d_in[0];
    const float* centers = (const float*)d_in[1];
    const float* sigma   = (const float*)d_in[2];
    float* out = (float*)d_out;

    int N = in_sizes[0] / DD;
    int M = in_sizes[1] / DD;

    const int PRE_SMEM = 128 * KPAD * 2;   // 50 KB
    cudaFuncSetAttribute(rbf_precompute_A, cudaFuncAttributeMaxDynamicSharedMemorySize, PRE_SMEM);
    cudaFuncSetAttribute(rbf_precompute_B, cudaFuncAttributeMaxDynamicSharedMemorySize, PRE_SMEM);
    rbf_precompute_B<<<M / 128, 128, PRE_SMEM>>>(centers, sigma, M);
    rbf_precompute_A<<<N / 128, 128, PRE_SMEM>>>(x, N);

    const int SMEM_BYTES = TNPTS * KPAD * 2 + TMC * KPAD * 2 + TMC * 4;  // ~102.9 KB
    cudaFuncSetAttribute(rbf_gemm, cudaFuncAttributeMaxDynamicSharedMemorySize, SMEM_BYTES);

    dim3 grid(M / TMC, N / TNPTS);
    rbf_gemm<<<grid, 256, SMEM_BYTES>>>(out, N, M);
}

// round 7
// speedup vs baseline: 3.2039x; 1.2681x over previous
#include <cuda_runtime.h>
#include <cuda_bf16.h>
#include <cstdint>

#define DD    32
#define KK    192          // 6 groups of 32: A=(qh,qh,ql,ph,ph,pl) * B=(wh,wl,wh,ah,al,ah)
#define KPAD  200          // bf16 per smem row: 400B stride -> ldmatrix conflict-free
#define NROW  24           // int4 chunks per 192-bf16 row
#define TNPTS 128
#define TMC   128
#define NMAX  16384
#define MMAX  1024

__device__ __nv_bfloat16 g_A[NMAX * KK];  // [n][k] bf16 split of (x^2, x)
__device__ __nv_bfloat16 g_B[MMAX * KK];  // [m][k] bf16, CEXP pre-folded
__device__ float g_eb[MMAX];              // CEXP*sum(c^2/s^2) + log2(1/detS)

// ---------------- helpers ----------------
__device__ __forceinline__ uint32_t smem_u32(const void* p) {
    uint32_t a;
    asm("{ .reg .u64 t; cvta.to.shared.u64 t, %1; cvt.u32.u64 %0, t; }" : "=r"(a) : "l"(p));
    return a;
}
__device__ __forceinline__ float ex2(float v) {
    float r; asm("ex2.approx.ftz.f32 %0, %1;" : "=f"(r) : "f"(v)); return r;
}
__device__ __forceinline__ void cp16(uint32_t smem_addr, const void* gptr) {
    asm volatile("cp.async.cg.shared.global [%0], [%1], 16;" :: "r"(smem_addr), "l"(gptr));
}
__device__ __forceinline__ void ldsm_x4(uint32_t& r0, uint32_t& r1, uint32_t& r2, uint32_t& r3,
                                        uint32_t addr) {
    asm volatile("ldmatrix.sync.aligned.m8n8.x4.shared.b16 {%0,%1,%2,%3}, [%4];"
                 : "=r"(r0), "=r"(r1), "=r"(r2), "=r"(r3) : "r"(addr));
}
__device__ __forceinline__ void mma_bf16(float* c, const uint32_t* a, uint32_t b0, uint32_t b1) {
    asm volatile(
        "mma.sync.aligned.m16n8k16.row.col.f32.bf16.bf16.f32 "
        "{%0,%1,%2,%3}, {%4,%5,%6,%7}, {%8,%9}, {%0,%1,%2,%3};"
        : "+f"(c[0]), "+f"(c[1]), "+f"(c[2]), "+f"(c[3])
        : "r"(a[0]), "r"(a[1]), "r"(a[2]), "r"(a[3]), "r"(b0), "r"(b1));
}
__device__ __forceinline__ __nv_bfloat16 bfh(float v) { return __float2bfloat16_rn(v); }

// ---------------- precompute A: one lane per (n, d) ----------------
__global__ __launch_bounds__(256) void rbf_precompute_A(const float* __restrict__ x, int N) {
    int idx = blockIdx.x * 256 + threadIdx.x;   // idx = n*32 + d
    int n = idx >> 5;
    int d = idx & 31;
    float v = x[idx];                            // coalesced
    __nv_bfloat16 ph = bfh(v);
    __nv_bfloat16 pl = bfh(v - __bfloat162float(ph));
    float q = v * v;
    __nv_bfloat16 qh = bfh(q);
    __nv_bfloat16 ql = bfh(q - __bfloat162float(qh));
    __nv_bfloat16* row = g_A + (size_t)n * KK + d;
    row[0 * 32] = qh;  row[1 * 32] = qh;  row[2 * 32] = ql;
    row[3 * 32] = ph;  row[4 * 32] = ph;  row[5 * 32] = pl;
}

// ---------------- precompute B + eb: one lane per (m, d), warp reductions ----------------
__global__ __launch_bounds__(256) void rbf_precompute_B(const float* __restrict__ centers,
                                                        const float* __restrict__ sigma, int M) {
    int idx = blockIdx.x * 256 + threadIdx.x;   // idx = m*32 + d
    int m = idx >> 5;
    int d = idx & 31;
    const float CEXP = -0.7213475204444817f;    // -0.5 * log2(e)
    const float LOG2_2PI = 2.6514961294723187f;

    float c  = centers[idx];
    float s  = sigma[idx];
    float s2 = s * s;
    float inv = __frcp_rn(s2);
    float w  = CEXP * inv;
    float a  = -2.0f * c * w;
    __nv_bfloat16 wh = bfh(w);
    __nv_bfloat16 wl = bfh(w - __bfloat162float(wh));
    __nv_bfloat16 ah = bfh(a);
    __nv_bfloat16 al = bfh(a - __bfloat162float(ah));
    __nv_bfloat16* row = g_B + (size_t)m * KK + d;
    row[0 * 32] = wh;  row[1 * 32] = wl;  row[2 * 32] = wh;
    row[3 * 32] = ah;  row[4 * 32] = al;  row[5 * 32] = ah;

    // warp-reduce cm = sum c^2/s^2 and lg = sum log2(s2) across the 32 dims
    float cm = c * c * inv;
    float lg = __log2f(s2);
#pragma unroll
    for (int o = 16; o > 0; o >>= 1) {
        cm += __shfl_xor_sync(0xFFFFFFFFu, cm, o);
        lg += __shfl_xor_sync(0xFFFFFFFFu, lg, o);
    }
    if (d == 0)
        g_eb[m] = fmaf(CEXP, cm, -0.5f * (DD * LOG2_2PI + lg));
}

// ---------------- main GEMM + exp epilogue ----------------
__global__ __launch_bounds__(256, 2)
void rbf_gemm(float* __restrict__ out, int N, int M) {
    extern __shared__ char dyn[];
    __nv_bfloat16* a_s  = (__nv_bfloat16*)dyn;            // [128][KPAD]
    __nv_bfloat16* b_s  = a_s + TNPTS * KPAD;             // [128][KPAD]
    float*         eb_s = (float*)(b_s + TMC * KPAD);     // [128]

    const int tid  = threadIdx.x;
    const int wid  = tid >> 5;
    const int lane = tid & 31;
    const int n0 = blockIdx.y * TNPTS;
    const int m0 = blockIdx.x * TMC;

    // --- Async tile loads: A then B, 24 int4/row, conflict-free, coalesced ---
    {
        uint32_t a_u = smem_u32(a_s), b_u = smem_u32(b_s);
        for (int i = tid; i < TNPTS * NROW; i += 256) {
            int r = i / NROW, c = i - r * NROW;
            cp16(a_u + (uint32_t)(r * (KPAD * 2) + c * 16),
                 (const char*)(g_A + (size_t)(n0 + r) * KK) + c * 16);
        }
        for (int i = tid; i < TMC * NROW; i += 256) {
            int r = i / NROW, c = i - r * NROW;
            cp16(b_u + (uint32_t)(r * (KPAD * 2) + c * 16),
                 (const char*)(g_B + (size_t)(m0 + r) * KK) + c * 16);
        }
        asm volatile("cp.async.commit_group;" ::: "memory");
    }
    if (tid < TMC) eb_s[tid] = g_eb[m0 + tid];
    asm volatile("cp.async.wait_group 0;" ::: "memory");
    __syncthreads();

    // --- Warp tiling: 2 (m) x 4 (n) warps; warp tile 64 x 32 ---
    const int warp_m = (wid & 1) * 64;
    const int warp_n = (wid >> 1) * 32;

    uint32_t a_base = smem_u32(a_s) + (uint32_t)(warp_m + (lane & 15)) * (KPAD * 2)
                    + ((uint32_t)lane >> 4) * 16u;
    uint32_t b_base = smem_u32(b_s)
                    + (uint32_t)(warp_n + ((lane >> 4) & 1) * 8 + (lane & 7)) * (KPAD * 2)
                    + (uint32_t)((lane >> 3) & 1) * 16u;

    float acc[4][4][4];
#pragma unroll
    for (int i = 0; i < 4; i++)
#pragma unroll
        for (int j = 0; j < 4; j++)
#pragma unroll
            for (int k = 0; k < 4; k++) acc[i][j][k] = 0.0f;

#pragma unroll
    for (int s = 0; s < KK / 16; s++) {
        uint32_t af[4][4];
#pragma unroll
        for (int mi = 0; mi < 4; mi++)
            ldsm_x4(af[mi][0], af[mi][1], af[mi][2], af[mi][3],
                    a_base + (uint32_t)mi * (16 * KPAD * 2) + (uint32_t)s * 32u);
        uint32_t bf[4][2];
#pragma unroll
        for (int nj2 = 0; nj2 < 2; nj2++) {
            uint32_t r0, r1, r2, r3;
            ldsm_x4(r0, r1, r2, r3,
                    b_base + (uint32_t)nj2 * (16 * KPAD * 2) + (uint32_t)s * 32u);
            bf[nj2 * 2 + 0][0] = r0; bf[nj2 * 2 + 0][1] = r1;
            bf[nj2 * 2 + 1][0] = r2; bf[nj2 * 2 + 1][1] = r3;
        }
#pragma unroll
        for (int mi = 0; mi < 4; mi++)
#pragma unroll
            for (int nt = 0; nt < 4; nt++)
                mma_bf16(acc[mi][nt], af[mi], bf[nt][0], bf[nt][1]);
    }

    // --- Epilogue: out = exp2(acc + eb) ---
    const int qrow = lane >> 2;
    const int qcol = 2 * (lane & 3);
#pragma unroll
    for (int mi = 0; mi < 4; mi++) {
        int row0 = n0 + warp_m + mi * 16 + qrow;
#pragma unroll
        for (int nt = 0; nt < 4; nt++) {
            int col_l = warp_n + nt * 8 + qcol;
            float2 ebv = *(const float2*)(eb_s + col_l);
            float* p0 = out + (size_t)row0 * M + m0 + col_l;
            float2 r0, r1;
            r0.x = ex2(acc[mi][nt][0] + ebv.x);
            r0.y = ex2(acc[mi][nt][1] + ebv.y);
            r1.x = ex2(acc[mi][nt][2] + ebv.x);
            r1.y = ex2(acc[mi][nt][3] + ebv.y);
            *(float2*)(p0) = r0;
            *(float2*)(p0 + (size_t)8 * M) = r1;
        }
    }
}

extern "C" void kernel_launch(void* const* d_in, const int* in_sizes, int n_in,
                              void* d_out, int out_size) {
    const float* x       = (const float*)d_in[0];
    const float* centers = (const float*)d_in[1];
    const float* sigma   = (const float*)d_in[2];
    float* out = (float*)d_out;

    int N = in_sizes[0] / DD;
    int M = in_sizes[1] / DD;

    rbf_precompute_B<<<(M * DD) / 256, 256>>>(centers, sigma, M);
    rbf_precompute_A<<<(N * DD) / 256, 256>>>(x, N);

    const int SMEM_BYTES = TNPTS * KPAD * 2 + TMC * KPAD * 2 + TMC * 4;  // ~102.9 KB
    cudaFuncSetAttribute(rbf_gemm, cudaFuncAttributeMaxDynamicSharedMemorySize, SMEM_BYTES);

    dim3 grid(M / TMC, N / TNPTS);
    rbf_gemm<<<grid, 256, SMEM_BYTES>>>(out, N, M);
}

// round 8
// speedup vs baseline: 3.5757x; 1.1160x over previous
#include <cuda_runtime.h>
#include <cuda_bf16.h>
#include <cstdint>

#define DD    32
#define KK    192          // 6 groups of 32: A=(qh,qh,ql,ph,ph,pl) * B=(wh,wl,wh,ah,al,ah)
#define KPAD  200          // bf16 per smem row: 400B stride -> ldmatrix conflict-free
#define NROW  24           // int4 chunks per 192-bf16 row
#define TNPTS 128
#define TMC   128
#define NMAX  16384
#define MMAX  1024

__device__ __nv_bfloat16 g_A[NMAX * KK];  // [n][k] bf16 split of (x^2, x)
__device__ __nv_bfloat16 g_B[MMAX * KK];  // [m][k] bf16, CEXP pre-folded
__device__ float g_eb[MMAX];              // CEXP*sum(c^2/s^2) + log2(1/detS)

// ---------------- helpers ----------------
__device__ __forceinline__ uint32_t smem_u32(const void* p) {
    uint32_t a;
    asm("{ .reg .u64 t; cvta.to.shared.u64 t, %1; cvt.u32.u64 %0, t; }" : "=r"(a) : "l"(p));
    return a;
}
__device__ __forceinline__ float ex2(float v) {
    float r; asm("ex2.approx.ftz.f32 %0, %1;" : "=f"(r) : "f"(v)); return r;
}
__device__ __forceinline__ void cp16(uint32_t smem_addr, const void* gptr) {
    asm volatile("cp.async.cg.shared.global [%0], [%1], 16;" :: "r"(smem_addr), "l"(gptr));
}
__device__ __forceinline__ void ldsm_x4(uint32_t& r0, uint32_t& r1, uint32_t& r2, uint32_t& r3,
                                        uint32_t addr) {
    asm volatile("ldmatrix.sync.aligned.m8n8.x4.shared.b16 {%0,%1,%2,%3}, [%4];"
                 : "=r"(r0), "=r"(r1), "=r"(r2), "=r"(r3) : "r"(addr));
}
__device__ __forceinline__ void mma_bf16(float* c, const uint32_t* a, uint32_t b0, uint32_t b1) {
    asm volatile(
        "mma.sync.aligned.m16n8k16.row.col.f32.bf16.bf16.f32 "
        "{%0,%1,%2,%3}, {%4,%5,%6,%7}, {%8,%9}, {%0,%1,%2,%3};"
        : "+f"(c[0]), "+f"(c[1]), "+f"(c[2]), "+f"(c[3])
        : "r"(a[0]), "r"(a[1]), "r"(a[2]), "r"(a[3]), "r"(b0), "r"(b1));
}
__device__ __forceinline__ __nv_bfloat16 bfh(float v) { return __float2bfloat16_rn(v); }

// ---------------- fused precompute: one lane per (row, d) ----------------
__global__ __launch_bounds__(256) void rbf_precompute(const float* __restrict__ x,
                                                      const float* __restrict__ centers,
                                                      const float* __restrict__ sigma,
                                                      int N, int M) {
    int idx = blockIdx.x * 256 + threadIdx.x;   // idx = n*32 + d
    int d = idx & 31;

    // --- A side (all idx < N*32) ---
    {
        int n = idx >> 5;
        float v = x[idx];                        // coalesced
        __nv_bfloat16 ph = bfh(v);
        __nv_bfloat16 pl = bfh(v - __bfloat162float(ph));
        float q = v * v;
        __nv_bfloat16 qh = bfh(q);
        __nv_bfloat16 ql = bfh(q - __bfloat162float(qh));
        __nv_bfloat16* row = g_A + (size_t)n * KK + d;
        row[0 * 32] = qh;  row[1 * 32] = qh;  row[2 * 32] = ql;
        row[3 * 32] = ph;  row[4 * 32] = ph;  row[5 * 32] = pl;
    }

    // --- B side (first M*32 lanes) ---
    if (idx < M * DD) {
        int m = idx >> 5;
        const float CEXP = -0.7213475204444817f;    // -0.5 * log2(e)
        const float LOG2_2PI = 2.6514961294723187f;
        float c  = centers[idx];
        float s  = sigma[idx];
        float s2 = s * s;
        float inv = __frcp_rn(s2);
        float w  = CEXP * inv;
        float a  = -2.0f * c * w;
        __nv_bfloat16 wh = bfh(w);
        __nv_bfloat16 wl = bfh(w - __bfloat162float(wh));
        __nv_bfloat16 ah = bfh(a);
        __nv_bfloat16 al = bfh(a - __bfloat162float(ah));
        __nv_bfloat16* row = g_B + (size_t)m * KK + d;
        row[0 * 32] = wh;  row[1 * 32] = wl;  row[2 * 32] = wh;
        row[3 * 32] = ah;  row[4 * 32] = al;  row[5 * 32] = ah;

        float cm = c * c * inv;
        float lg = __log2f(s2);
#pragma unroll
        for (int o = 16; o > 0; o >>= 1) {
            cm += __shfl_xor_sync(0xFFFFFFFFu, cm, o);
            lg += __shfl_xor_sync(0xFFFFFFFFu, lg, o);
        }
        if (d == 0)
            g_eb[m] = fmaf(CEXP, cm, -0.5f * (DD * LOG2_2PI + lg));
    }
}

// ---------------- main GEMM + exp epilogue: 4 warps, warp tile 64x64 ----------------
__global__ __launch_bounds__(128, 2)
void rbf_gemm(float* __restrict__ out, int N, int M) {
    extern __shared__ char dyn[];
    __nv_bfloat16* a_s  = (__nv_bfloat16*)dyn;            // [128][KPAD]
    __nv_bfloat16* b_s  = a_s + TNPTS * KPAD;             // [128][KPAD]
    float*         eb_s = (float*)(b_s + TMC * KPAD);     // [128]

    const int tid  = threadIdx.x;
    const int wid  = tid >> 5;
    const int lane = tid & 31;
    const int n0 = blockIdx.y * TNPTS;
    const int m0 = blockIdx.x * TMC;

    // --- Async tile loads: A then B, 24 int4/row, conflict-free, coalesced ---
    {
        uint32_t a_u = smem_u32(a_s), b_u = smem_u32(b_s);
        for (int i = tid; i < TNPTS * NROW; i += 128) {
            int r = i / NROW, c = i - r * NROW;
            cp16(a_u + (uint32_t)(r * (KPAD * 2) + c * 16),
                 (const char*)(g_A + (size_t)(n0 + r) * KK) + c * 16);
        }
        for (int i = tid; i < TMC * NROW; i += 128) {
            int r = i / NROW, c = i - r * NROW;
            cp16(b_u + (uint32_t)(r * (KPAD * 2) + c * 16),
                 (const char*)(g_B + (size_t)(m0 + r) * KK) + c * 16);
        }
        asm volatile("cp.async.commit_group;" ::: "memory");
    }
    eb_s[tid] = g_eb[m0 + tid];
    asm volatile("cp.async.wait_group 0;" ::: "memory");
    __syncthreads();

    // --- Warp tiling: 2 (m) x 2 (n) warps; warp tile 64 x 64 ---
    const int warp_m = (wid & 1) * 64;
    const int warp_n = (wid >> 1) * 64;

    uint32_t a_base = smem_u32(a_s) + (uint32_t)(warp_m + (lane & 15)) * (KPAD * 2)
                    + ((uint32_t)lane >> 4) * 16u;
    uint32_t b_base = smem_u32(b_s)
                    + (uint32_t)(warp_n + ((lane >> 4) & 1) * 8 + (lane & 7)) * (KPAD * 2)
                    + (uint32_t)((lane >> 3) & 1) * 16u;

    float acc[4][8][4];
#pragma unroll
    for (int i = 0; i < 4; i++)
#pragma unroll
        for (int j = 0; j < 8; j++)
#pragma unroll
            for (int k = 0; k < 4; k++) acc[i][j][k] = 0.0f;

#pragma unroll
    for (int s = 0; s < KK / 16; s++) {
        uint32_t af[4][4];
#pragma unroll
        for (int mi = 0; mi < 4; mi++)
            ldsm_x4(af[mi][0], af[mi][1], af[mi][2], af[mi][3],
                    a_base + (uint32_t)mi * (16 * KPAD * 2) + (uint32_t)s * 32u);
        uint32_t bf[8][2];
#pragma unroll
        for (int nj2 = 0; nj2 < 4; nj2++) {
            uint32_t r0, r1, r2, r3;
            ldsm_x4(r0, r1, r2, r3,
                    b_base + (uint32_t)nj2 * (16 * KPAD * 2) + (uint32_t)s * 32u);
            bf[nj2 * 2 + 0][0] = r0; bf[nj2 * 2 + 0][1] = r1;
            bf[nj2 * 2 + 1][0] = r2; bf[nj2 * 2 + 1][1] = r3;
        }
#pragma unroll
        for (int mi = 0; mi < 4; mi++)
#pragma unroll
            for (int nt = 0; nt < 8; nt++)
                mma_bf16(acc[mi][nt], af[mi], bf[nt][0], bf[nt][1]);
    }

    // --- Epilogue: out = exp2(acc + eb) ---
    const int qrow = lane >> 2;
    const int qcol = 2 * (lane & 3);
#pragma unroll
    for (int mi = 0; mi < 4; mi++) {
        int row0 = n0 + warp_m + mi * 16 + qrow;
#pragma unroll
        for (int nt = 0; nt < 8; nt++) {
            int col_l = warp_n + nt * 8 + qcol;
            float2 ebv = *(const float2*)(eb_s + col_l);
            float* p0 = out + (size_t)row0 * M + m0 + col_l;
            float2 r0, r1;
            r0.x = ex2(acc[mi][nt][0] + ebv.x);
            r0.y = ex2(acc[mi][nt][1] + ebv.y);
            r1.x = ex2(acc[mi][nt][2] + ebv.x);
            r1.y = ex2(acc[mi][nt][3] + ebv.y);
            *(float2*)(p0) = r0;
            *(float2*)(p0 + (size_t)8 * M) = r1;
        }
    }
}

extern "C" void kernel_launch(void* const* d_in, const int* in_sizes, int n_in,
                              void* d_out, int out_size) {
    const float* x       = (const float*)d_in[0];
    const float* centers = (const float*)d_in[1];
    const float* sigma   = (const float*)d_in[2];
    float* out = (float*)d_out;

    int N = in_sizes[0] / DD;
    int M = in_sizes[1] / DD;

    rbf_precompute<<<(N * DD) / 256, 256>>>(x, centers, sigma, N, M);

    const int SMEM_BYTES = TNPTS * KPAD * 2 + TMC * KPAD * 2 + TMC * 4;  // ~102.9 KB
    cudaFuncSetAttribute(rbf_gemm, cudaFuncAttributeMaxDynamicSharedMemorySize, SMEM_BYTES);

    dim3 grid(M / TMC, N / TNPTS);
    rbf_gemm<<<grid, 128, SMEM_BYTES>>>(out, N, M);
}